// round 11
// baseline (speedup 1.0000x reference)
#include <cuda_runtime.h>

#define T_ 1024
#define B_ 128
#define L_ 128
#define STRIDE_ (B_ * L_)

typedef unsigned long long ull;

// scratch (no allocations allowed)
__device__ float g_den[B_];
__device__ float g_num[B_];

__device__ __forceinline__ ull ffma2(ull a, ull b, ull c) {
    ull d;
    asm("fma.rn.f32x2 %0, %1, %2, %3;" : "=l"(d) : "l"(a), "l"(b), "l"(c));
    return d;
}
__device__ __forceinline__ ull add2(ull a, ull b) {
    ull d;
    asm("add.rn.f32x2 %0, %1, %2;" : "=l"(d) : "l"(a), "l"(b));
    return d;
}
__device__ __forceinline__ ull pack2(float lo, float hi) {
    ull d;
    asm("mov.b64 %0, {%1, %2};" : "=l"(d) : "f"(lo), "f"(hi));
    return d;
}
__device__ __forceinline__ float2 unpack2(ull v) {
    float2 f;
    asm("mov.b64 {%0, %1}, %2;" : "=f"(f.x), "=f"(f.y) : "l"(v));
    return f;
}

#define CBAR(id) asm volatile("bar.sync %0, 256;" :: "r"(id) : "memory")

// den = log(e_endT · M_1023···M_1 · u_0) with
//   (M_t x)[j] = exp(p_t[j]) * sum_i expT[i][j] x[i]   (identity if mask=0).
// Product split: forward half u_A = M_511···M_1 u_0 (511 steps), backward
// half v_B = M_512^T···M_1023^T e_end (512 steps);
//   den = logZ_A + logZ_B + log(u_A · v_B).
// This kernel runs BOTH half-chains in one 512-thread CTA (grid = 128), and
// additionally 2-way lane-slices each chain's dot product:
//   chain = tid>>8, r = tid&255, j = r>>1 (state), s = r&1 (i-slice half).
// Each SMSP then holds 4 warps of mutually independent work (2 chains x 2
// slices) -> dependency stalls are hidden. Slice partners are adjacent lanes:
// partials combine with one shfl_xor(1). Renormalize by broadcast element 0
// of the exchanged vector every 4 steps (exact; measured rel_err 0).

// half-dot: 64 floats at BASE_ against rT2[0..31] (32 FFMA2, 8 accumulators)
#define DOT64(BASE_, PART_)                                                   \
    do {                                                                      \
        const ulonglong2* ev = reinterpret_cast<const ulonglong2*>(BASE_);    \
        ull c0 = 0ull, c1 = 0ull, c2 = 0ull, c3 = 0ull;                       \
        ull c4 = 0ull, c5 = 0ull, c6 = 0ull, c7 = 0ull;                       \
        _Pragma("unroll")                                                     \
        for (int i = 0; i < 4; ++i) {                                         \
            ulonglong2 x = ev[4 * i];                                         \
            ulonglong2 y = ev[4 * i + 1];                                     \
            ulonglong2 z = ev[4 * i + 2];                                     \
            ulonglong2 q = ev[4 * i + 3];                                     \
            c0 = ffma2(x.x, rT2[8 * i + 0], c0);                              \
            c1 = ffma2(x.y, rT2[8 * i + 1], c1);                              \
            c2 = ffma2(y.x, rT2[8 * i + 2], c2);                              \
            c3 = ffma2(y.y, rT2[8 * i + 3], c3);                              \
            c4 = ffma2(z.x, rT2[8 * i + 4], c4);                              \
            c5 = ffma2(z.y, rT2[8 * i + 5], c5);                              \
            c6 = ffma2(q.x, rT2[8 * i + 6], c6);                              \
            c7 = ffma2(q.y, rT2[8 * i + 7], c7);                              \
        }                                                                     \
        c0 = add2(c0, c1); c2 = add2(c2, c3);                                 \
        c4 = add2(c4, c5); c6 = add2(c6, c7);                                 \
        c0 = add2(c0, c2); c4 = add2(c4, c6);                                 \
        c0 = add2(c0, c4);                                                    \
        float2 fx = unpack2(c0);                                              \
        PART_ = fx.x + fx.y;                                                  \
    } while (0)

__global__ __launch_bounds__(512, 1) void crf_den_kernel(
    const float* __restrict__ pred,    // (T,B,L)
    const int*   __restrict__ mask,    // (T,B)
    const float* __restrict__ trans,   // (L,L)
    const float* __restrict__ start,   // (L)
    const float* __restrict__ endv)    // (L)
{
    const int tid   = threadIdx.x;
    const int chain = tid >> 8;          // 0 = forward half, 1 = backward half
    const int r     = tid & 255;
    const int j     = r >> 1;            // state 0..127
    const int s     = r & 1;             // i-slice half
    const int lane  = tid & 31;
    const int wid   = tid >> 5;          // 0..15 (chain 0: 0..7)
    const int b     = blockIdx.x;

    __shared__ __align__(16) float eA[2][L_];
    __shared__ __align__(16) float eB[2][L_];
    __shared__ int   m_sh[T_];
    __shared__ float red[8];
    __shared__ float zsh[2];

    for (int t = tid; t < T_; t += 512)
        m_sh[t] = mask[t * B_ + b];

    const float* pj = pred + b * L_ + j;

    // expT slice: fwd needs column j, rows [64s,64s+64); bwd needs row j,
    // cols [64s,64s+64). 32 packed regs.
    ull rT2[32];
    if (chain == 0) {
#pragma unroll
        for (int k = 0; k < 32; ++k) {
            const int i = (s << 6) + 2 * k;
            rT2[k] = pack2(expf(trans[i * L_ + j]),
                           expf(trans[(i + 1) * L_ + j]));
        }
    } else {
#pragma unroll
        for (int k = 0; k < 32; ++k) {
            const int jj = (s << 6) + 2 * k;
            rT2[k] = pack2(expf(trans[j * L_ + jj]),
                           expf(trans[j * L_ + jj + 1]));
        }
    }

    float u;              // chain 0: u_A[j] ; chain 1: v_B[j]
    float logZ = 0.0f;
    int   buf  = 0;

    if (chain == 0) {
        u = __expf(start[j] + pj[0]);   // u_0
        if (s == 0) eA[0][j] = u;
    } else {
        u = __expf(endv[j]);            // v_T
    }
    __syncthreads();   // init stores + m_sh visible

    if (chain == 0) {
        // ---------------- forward half: t = 1 .. 511 ----------------
        float pr0 = pj[(size_t)1 << 14];
        float pr1 = pj[(size_t)2 << 14];
        float pr2 = pj[(size_t)3 << 14];
        float pr3 = pj[(size_t)4 << 14];
        float ep_cur = __expf(pr0);
        int   mk_cur = m_sh[1];

#define FSTEP(t_, PRc_, PRn_, RN_)                                            \
    do {                                                                      \
        float part;                                                           \
        DOT64(&eA[buf][s << 6], part);                                        \
        part += __shfl_xor_sync(0xffffffffu, part, 1);                        \
        float inv_m = 1.0f;                                                   \
        if (RN_) {                                                            \
            const float mv = eA[buf][0];                                      \
            logZ += __logf(mv);                                               \
            inv_m = 1.0f / mv;                                                \
        }                                                                     \
        u = (mk_cur ? part * ep_cur : u) * inv_m;                             \
        buf ^= 1;                                                             \
        if (s == 0) eA[buf][j] = u;                                           \
        CBAR(1);                                                              \
        PRc_ = pj[(size_t)((t_) + 4) << 14];  /* t+4 <= 515, in-bounds */     \
        ep_cur = __expf(PRn_);                                                \
        mk_cur = m_sh[(t_) + 1];                                              \
    } while (0)

        for (int tb = 1; tb + 3 <= 508; tb += 4) {   // t = 1 .. 508
            FSTEP(tb + 0, pr0, pr1, false);
            FSTEP(tb + 1, pr1, pr2, false);
            FSTEP(tb + 2, pr2, pr3, false);
            FSTEP(tb + 3, pr3, pr0, true);
        }
        FSTEP(509, pr0, pr1, false);
        FSTEP(510, pr1, pr2, false);
        FSTEP(511, pr2, pr3, false);
#undef FSTEP
    } else {
        // ---------------- backward half: t = 1023 .. 512 ----------------
        float pr0 = pj[(size_t)1023 << 14];
        float pr1 = pj[(size_t)1022 << 14];
        float pr2 = pj[(size_t)1021 << 14];
        float pr3 = pj[(size_t)1020 << 14];
        float ep_cur = __expf(pr0);
        int   mk_cur = m_sh[1023];

#define BSTEP(t_, PRc_, PRn_, RN_)                                            \
    do {                                                                      \
        if (s == 0) eB[buf][j] = ep_cur * u;  /* w = ep_t ⊙ v */              \
        CBAR(2);                                                              \
        float part;                                                           \
        DOT64(&eB[buf][s << 6], part);                                        \
        part += __shfl_xor_sync(0xffffffffu, part, 1);                        \
        float inv_m = 1.0f;                                                   \
        if (RN_) {                                                            \
            const float mv = eB[buf][0];                                      \
            logZ += __logf(mv);                                               \
            inv_m = 1.0f / mv;                                                \
        }                                                                     \
        u = (mk_cur ? part : u) * inv_m;                                      \
        buf ^= 1;                                                             \
        PRc_ = pj[(size_t)((t_) - 4) << 14];  /* t-4 >= 508, in-bounds */     \
        ep_cur = __expf(PRn_);                                                \
        mk_cur = m_sh[(t_) - 1];                                              \
    } while (0)

        for (int tb = 1023; tb - 3 >= 512; tb -= 4) {   // t = 1023 .. 512
            BSTEP(tb - 0, pr0, pr1, false);
            BSTEP(tb - 1, pr1, pr2, false);
            BSTEP(tb - 2, pr2, pr3, false);
            BSTEP(tb - 3, pr3, pr0, true);
        }
#undef BSTEP
    }

    __syncthreads();   // both halves done

    // publish final vectors + partial logZs
    if (chain == 0) { if (s == 0) eA[0][j] = u; }
    else            { if (s == 0) eB[0][j] = u; }
    if (r == 0) zsh[chain] = logZ;
    __syncthreads();

    // den[b] = logZ_A + logZ_B + log( sum_j u_A[j] * v_B[j] )
    if (chain == 0) {
        float v = (s == 0) ? eA[0][j] * eB[0][j] : 0.0f;
#pragma unroll
        for (int off = 16; off; off >>= 1)
            v += __shfl_xor_sync(0xffffffffu, v, off);
        if (lane == 0) red[wid] = v;
    }
    __syncthreads();
    if (tid == 0) {
        float sum = 0.0f;
#pragma unroll
        for (int q = 0; q < 8; ++q) sum += red[q];
        g_den[b] = zsh[0] + zsh[1] + __logf(sum);
    }
}

// ---------------------------------------------------------------------------
// Numerator: path score. One block per batch b, 256 threads stride over t.
// Targets may be int64 or int32 (JAX x64 off) — sniff at runtime.
// ---------------------------------------------------------------------------
__global__ __launch_bounds__(256) void crf_num_kernel(
    const float* __restrict__ pred,
    const void*  __restrict__ tgt_raw,
    const int*   __restrict__ mask,
    const float* __restrict__ trans,
    const float* __restrict__ start,
    const float* __restrict__ endv)
{
    const int b    = blockIdx.x;
    const int tid  = threadIdx.x;
    const int lane = tid & 31;
    const int wid  = tid >> 5;

    __shared__ int s_is64;
    if (tid == 0) {
        const unsigned int* wp = (const unsigned int*)tgt_raw;
        int is64 = 1;
#pragma unroll
        for (int k = 0; k < 32; ++k)
            if (wp[2 * k + 1] != 0u) { is64 = 0; break; }
        s_is64 = is64;
    }
    __syncthreads();
    const int is64 = s_is64;
    const long long* t64 = (const long long*)tgt_raw;
    const int*       t32 = (const int*)tgt_raw;

    float local = 0.0f;
    int   mcnt  = 0;

    for (int t = tid; t < T_; t += 256) {
        const int mk = mask[t * B_ + b];
        mcnt += mk;
        if (t >= 1 && mk) {
            const int cur = is64 ? (int)t64[t * B_ + b]       : t32[t * B_ + b];
            const int prv = is64 ? (int)t64[(t - 1) * B_ + b] : t32[(t - 1) * B_ + b];
            local += trans[prv * L_ + cur] +
                     pred[(size_t)t * STRIDE_ + b * L_ + cur];
        }
    }

    __shared__ float sf[8];
    __shared__ int   si[8];
#pragma unroll
    for (int off = 16; off; off >>= 1) {
        local += __shfl_xor_sync(0xffffffffu, local, off);
        mcnt  += __shfl_xor_sync(0xffffffffu, mcnt,  off);
    }
    if (lane == 0) { sf[wid] = local; si[wid] = mcnt; }
    __syncthreads();

    if (tid == 0) {
        float tot = 0.0f;
        int   mt  = 0;
#pragma unroll
        for (int q = 0; q < 8; ++q) { tot += sf[q]; mt += si[q]; }
        const int t0 = is64 ? (int)t64[b] : t32[b];
        float sc = start[t0] + pred[b * L_ + t0] + tot;
        const int last = mt - 1;
        const int tl = is64 ? (int)t64[last * B_ + b] : t32[last * B_ + b];
        sc += endv[tl];
        g_num[b] = sc;
    }
}

// ---------------------------------------------------------------------------
// Final: out = mean(den - num)
// ---------------------------------------------------------------------------
__global__ __launch_bounds__(B_) void crf_final_kernel(float* __restrict__ out)
{
    const int j    = threadIdx.x;
    const int lane = j & 31;
    const int wid  = j >> 5;

    float v = g_den[j] - g_num[j];
    __shared__ float red[4];
#pragma unroll
    for (int off = 16; off; off >>= 1)
        v += __shfl_xor_sync(0xffffffffu, v, off);
    if (lane == 0) red[wid] = v;
    __syncthreads();
    if (j == 0)
        out[0] = ((red[0] + red[1]) + (red[2] + red[3])) * (1.0f / (float)B_);
}

extern "C" void kernel_launch(void* const* d_in, const int* in_sizes, int n_in,
                              void* d_out, int out_size)
{
    const float* pred  = (const float*)d_in[0];
    const void*  tgt   = (const void*)d_in[1];
    const int*   mask  = (const int*)d_in[2];
    const float* trans = (const float*)d_in[3];
    const float* start = (const float*)d_in[4];
    const float* endv  = (const float*)d_in[5];
    float* out = (float*)d_out;

    crf_den_kernel<<<B_, 512>>>(pred, mask, trans, start, endv);
    crf_num_kernel<<<B_, 256>>>(pred, tgt, mask, trans, start, endv);
    crf_final_kernel<<<1, B_>>>(out);
}

// round 12
// speedup vs baseline: 1.7151x; 1.7151x over previous
#include <cuda_runtime.h>

#define T_ 1024
#define B_ 128
#define L_ 128
#define STRIDE_ (B_ * L_)

typedef unsigned long long ull;

// scratch (no allocations allowed)
__device__ float g_den[B_];
__device__ float g_num[B_];

__device__ __forceinline__ ull ffma2(ull a, ull b, ull c) {
    ull d;
    asm("fma.rn.f32x2 %0, %1, %2, %3;" : "=l"(d) : "l"(a), "l"(b), "l"(c));
    return d;
}
__device__ __forceinline__ ull add2(ull a, ull b) {
    ull d;
    asm("add.rn.f32x2 %0, %1, %2;" : "=l"(d) : "l"(a), "l"(b));
    return d;
}
__device__ __forceinline__ ull pack2(float lo, float hi) {
    ull d;
    asm("mov.b64 %0, {%1, %2};" : "=l"(d) : "f"(lo), "f"(hi));
    return d;
}
__device__ __forceinline__ float2 unpack2(ull v) {
    float2 f;
    asm("mov.b64 {%0, %1}, %2;" : "=f"(f.x), "=f"(f.y) : "l"(v));
    return f;
}

#define CBAR(id) asm volatile("bar.sync %0, 128;" :: "r"(id) : "memory")

// den = log(e_endT · M_1023···M_1 · u_0) with
//   (M_t x)[j] = exp(p_t[j]) * sum_i expT[i][j] x[i]   (identity if mask=0).
// Product split: forward half u_A = M_511···M_1 u_0 (511 steps), backward
// half v_B = M_512^T···M_1023^T e_end (512 steps);
//   den = logZ_A + logZ_B + log(u_A · v_B).
// Both half-chains run in one 256-thread CTA (grid = 128): chain = tid>>7,
// j = tid&127. One warp of each chain per SMSP; the bwd chain is given a
// ~300-cycle skew preamble so the two chains run ANTI-PHASE on each
// scheduler (ladder of one overlaps barrier/LDS of the other) instead of
// colliding in lockstep. Renormalize by broadcast element 0 of the
// exchanged vector every 4 steps (exact; measured rel_err 0); the renorm
// log/rcp is hoisted before the dot so it completes in the dot's shadow.

// dot of exchanged vector (smem, pairs) against rT2 (64 packed regs)
#define DOT128(EVBASE_, PART_)                                                \
    do {                                                                      \
        const ulonglong2* ev = reinterpret_cast<const ulonglong2*>(EVBASE_);  \
        ull c0 = 0ull, c1 = 0ull, c2 = 0ull, c3 = 0ull;                       \
        ull c4 = 0ull, c5 = 0ull, c6 = 0ull, c7 = 0ull;                       \
        _Pragma("unroll")                                                     \
        for (int i = 0; i < 8; ++i) {                                         \
            ulonglong2 x = ev[4 * i];                                         \
            ulonglong2 y = ev[4 * i + 1];                                     \
            ulonglong2 z = ev[4 * i + 2];                                     \
            ulonglong2 q = ev[4 * i + 3];                                     \
            c0 = ffma2(x.x, rT2[8 * i + 0], c0);                              \
            c1 = ffma2(x.y, rT2[8 * i + 1], c1);                              \
            c2 = ffma2(y.x, rT2[8 * i + 2], c2);                              \
            c3 = ffma2(y.y, rT2[8 * i + 3], c3);                              \
            c4 = ffma2(z.x, rT2[8 * i + 4], c4);                              \
            c5 = ffma2(z.y, rT2[8 * i + 5], c5);                              \
            c6 = ffma2(q.x, rT2[8 * i + 6], c6);                              \
            c7 = ffma2(q.y, rT2[8 * i + 7], c7);                              \
        }                                                                     \
        c0 = add2(c0, c1); c2 = add2(c2, c3);                                 \
        c4 = add2(c4, c5); c6 = add2(c6, c7);                                 \
        c0 = add2(c0, c2); c4 = add2(c4, c6);                                 \
        c0 = add2(c0, c4);                                                    \
        float2 fx = unpack2(c0);                                              \
        PART_ = fx.x + fx.y;                                                  \
    } while (0)

__global__ __launch_bounds__(256, 1) void crf_den_kernel(
    const float* __restrict__ pred,    // (T,B,L)
    const int*   __restrict__ mask,    // (T,B)
    const float* __restrict__ trans,   // (L,L)
    const float* __restrict__ start,   // (L)
    const float* __restrict__ endv)    // (L)
{
    const int tid   = threadIdx.x;
    const int chain = tid >> 7;          // 0 = forward half, 1 = backward half
    const int j     = tid & 127;
    const int lane  = tid & 31;
    const int wloc  = (tid >> 5) & 3;
    const int b     = blockIdx.x;

    __shared__ __align__(16) float eA[2][L_];   // forward exchange
    __shared__ __align__(16) float eB[2][L_];   // backward exchange
    __shared__ int   m_sh[T_];
    __shared__ float red[4];
    __shared__ float zsh[2];

    // mask column b, loaded cooperatively by all 256 threads
    for (int t = tid; t < T_; t += 256)
        m_sh[t] = mask[t * B_ + b];

    const float* pj = pred + b * L_ + j;

    // exp(transitions): fwd thread j needs COLUMN j (pairs over i);
    // bwd thread j needs ROW j (pairs over the summed index jj).
    ull rT2[64];
    if (chain == 0) {
#pragma unroll
        for (int k = 0; k < 64; ++k)
            rT2[k] = pack2(expf(trans[(2 * k) * L_ + j]),
                           expf(trans[(2 * k + 1) * L_ + j]));
    } else {
#pragma unroll
        for (int k = 0; k < 64; ++k)
            rT2[k] = pack2(expf(trans[j * L_ + 2 * k]),
                           expf(trans[j * L_ + 2 * k + 1]));
    }

    float u;              // chain 0: u ; chain 1: v
    float logZ = 0.0f;
    int   buf  = 0;

    if (chain == 0) {
        u = __expf(start[j] + pj[0]);   // u_0
        eA[0][j] = u;
    } else {
        u = __expf(endv[j]);            // v_T
    }
    __syncthreads();   // init stores + m_sh visible to everyone

    if (chain == 0) {
        // ---------------- forward half: t = 1 .. 511 ----------------
        float pr0 = pj[(size_t)1 << 14];
        float pr1 = pj[(size_t)2 << 14];
        float pr2 = pj[(size_t)3 << 14];
        float pr3 = pj[(size_t)4 << 14];
        float ep_cur = __expf(pr0);
        int   mk_cur = m_sh[1];

#define FSTEP(t_, PRc_, PRn_, RN_)                                            \
    do {                                                                      \
        float inv_m = 1.0f;                                                   \
        if (RN_) {                        /* hoisted: runs in dot's shadow */ \
            const float mv = eA[buf][0];                                      \
            logZ += __logf(mv);                                               \
            inv_m = 1.0f / mv;                                                \
        }                                                                     \
        float part;                                                           \
        DOT128(&eA[buf][0], part);                                            \
        u = (mk_cur ? part * ep_cur : u) * inv_m;                             \
        buf ^= 1;                                                             \
        eA[buf][j] = u;                                                       \
        CBAR(1);                                                              \
        PRc_ = pj[(size_t)((t_) + 4) << 14];  /* t+4 <= 515, in-bounds */     \
        ep_cur = __expf(PRn_);                                                \
        mk_cur = m_sh[(t_) + 1];                                              \
    } while (0)

        for (int tb = 1; tb + 3 <= 508; tb += 4) {   // t = 1 .. 508
            FSTEP(tb + 0, pr0, pr1, false);
            FSTEP(tb + 1, pr1, pr2, false);
            FSTEP(tb + 2, pr2, pr3, false);
            FSTEP(tb + 3, pr3, pr0, true);
        }
        FSTEP(509, pr0, pr1, false);
        FSTEP(510, pr1, pr2, false);
        FSTEP(511, pr2, pr3, false);
#undef FSTEP
    } else {
        // ---------------- backward half: t = 1023 .. 512 ----------------
        float pr0 = pj[(size_t)1023 << 14];
        float pr1 = pj[(size_t)1022 << 14];
        float pr2 = pj[(size_t)1021 << 14];
        float pr3 = pj[(size_t)1020 << 14];
        float ep_cur = __expf(pr0);
        int   mk_cur = m_sh[1023];

        // ---- phase-skew preamble (~300 cyc): dependent FFMA2 chain so the
        // bwd chain runs anti-phase to the fwd chain on each SMSP. The chain
        // multiplies u's pack by (1+1e-7) 75 times (numerically negligible);
        // the impossible-bit-pattern compare sinks the result so neither
        // nvcc nor ptxas can delete the chain.
        {
            ull skew = pack2(u, u);
            const ull m1 = pack2(1.0000001f, 1.0000001f);
            const ull z0 = pack2(0.0f, 0.0f);
#pragma unroll
            for (int k = 0; k < 75; ++k)
                skew = ffma2(skew, m1, z0);
            if (__float_as_uint(unpack2(skew).x) == 0x7fc00123u)
                u = 0.0f;   // never taken
        }

#define BSTEP(t_, PRc_, PRn_, RN_)                                            \
    do {                                                                      \
        eB[buf][j] = ep_cur * u;        /* w = ep_t ⊙ v */                    \
        CBAR(2);                                                              \
        float inv_m = 1.0f;                                                   \
        if (RN_) {                        /* hoisted: runs in dot's shadow */ \
            const float mv = eB[buf][0];                                      \
            logZ += __logf(mv);                                               \
            inv_m = 1.0f / mv;                                                \
        }                                                                     \
        float part;                                                           \
        DOT128(&eB[buf][0], part);                                            \
        u = (mk_cur ? part : u) * inv_m;                                      \
        buf ^= 1;                                                             \
        PRc_ = pj[(size_t)((t_) - 4) << 14];  /* t-4 >= 508, in-bounds */     \
        ep_cur = __expf(PRn_);                                                \
        mk_cur = m_sh[(t_) - 1];                                              \
    } while (0)

        for (int tb = 1023; tb - 3 >= 512; tb -= 4) {   // t = 1023 .. 512
            BSTEP(tb - 0, pr0, pr1, false);
            BSTEP(tb - 1, pr1, pr2, false);
            BSTEP(tb - 2, pr2, pr3, false);
            BSTEP(tb - 3, pr3, pr0, true);
        }
#undef BSTEP
    }

    __syncthreads();   // both halves done

    // publish final vectors and partial logZs
    if (chain == 0) eA[0][j] = u;
    else            eB[0][j] = u;
    if (j == 0) zsh[chain] = logZ;
    __syncthreads();

    // den[b] = logZ_A + logZ_B + log( sum_j u_A[j] * v_B[j] )
    if (chain == 0) {
        float v = eA[0][j] * eB[0][j];
#pragma unroll
        for (int off = 16; off; off >>= 1)
            v += __shfl_xor_sync(0xffffffffu, v, off);
        if (lane == 0) red[wloc] = v;
    }
    __syncthreads();
    if (tid == 0) {
        float s = (red[0] + red[1]) + (red[2] + red[3]);
        g_den[b] = zsh[0] + zsh[1] + __logf(s);
    }
}

// ---------------------------------------------------------------------------
// Numerator: path score. One block per batch b, 256 threads stride over t.
// Targets may be int64 or int32 (JAX x64 off) — sniff at runtime.
// ---------------------------------------------------------------------------
__global__ __launch_bounds__(256) void crf_num_kernel(
    const float* __restrict__ pred,
    const void*  __restrict__ tgt_raw,
    const int*   __restrict__ mask,
    const float* __restrict__ trans,
    const float* __restrict__ start,
    const float* __restrict__ endv)
{
    const int b    = blockIdx.x;
    const int tid  = threadIdx.x;
    const int lane = tid & 31;
    const int wid  = tid >> 5;

    __shared__ int s_is64;
    if (tid == 0) {
        const unsigned int* wp = (const unsigned int*)tgt_raw;
        int is64 = 1;
#pragma unroll
        for (int k = 0; k < 32; ++k)
            if (wp[2 * k + 1] != 0u) { is64 = 0; break; }
        s_is64 = is64;
    }
    __syncthreads();
    const int is64 = s_is64;
    const long long* t64 = (const long long*)tgt_raw;
    const int*       t32 = (const int*)tgt_raw;

    float local = 0.0f;
    int   mcnt  = 0;

    for (int t = tid; t < T_; t += 256) {
        const int mk = mask[t * B_ + b];
        mcnt += mk;
        if (t >= 1 && mk) {
            const int cur = is64 ? (int)t64[t * B_ + b]       : t32[t * B_ + b];
            const int prv = is64 ? (int)t64[(t - 1) * B_ + b] : t32[(t - 1) * B_ + b];
            local += trans[prv * L_ + cur] +
                     pred[(size_t)t * STRIDE_ + b * L_ + cur];
        }
    }

    __shared__ float sf[8];
    __shared__ int   si[8];
#pragma unroll
    for (int off = 16; off; off >>= 1) {
        local += __shfl_xor_sync(0xffffffffu, local, off);
        mcnt  += __shfl_xor_sync(0xffffffffu, mcnt,  off);
    }
    if (lane == 0) { sf[wid] = local; si[wid] = mcnt; }
    __syncthreads();

    if (tid == 0) {
        float tot = 0.0f;
        int   mt  = 0;
#pragma unroll
        for (int q = 0; q < 8; ++q) { tot += sf[q]; mt += si[q]; }
        const int t0 = is64 ? (int)t64[b] : t32[b];
        float sc = start[t0] + pred[b * L_ + t0] + tot;
        const int last = mt - 1;
        const int tl = is64 ? (int)t64[last * B_ + b] : t32[last * B_ + b];
        sc += endv[tl];
        g_num[b] = sc;
    }
}

// ---------------------------------------------------------------------------
// Final: out = mean(den - num)
// ---------------------------------------------------------------------------
__global__ __launch_bounds__(B_) void crf_final_kernel(float* __restrict__ out)
{
    const int j    = threadIdx.x;
    const int lane = j & 31;
    const int wid  = j >> 5;

    float v = g_den[j] - g_num[j];
    __shared__ float red[4];
#pragma unroll
    for (int off = 16; off; off >>= 1)
        v += __shfl_xor_sync(0xffffffffu, v, off);
    if (lane == 0) red[wid] = v;
    __syncthreads();
    if (j == 0)
        out[0] = ((red[0] + red[1]) + (red[2] + red[3])) * (1.0f / (float)B_);
}

extern "C" void kernel_launch(void* const* d_in, const int* in_sizes, int n_in,
                              void* d_out, int out_size)
{
    const float* pred  = (const float*)d_in[0];
    const void*  tgt   = (const void*)d_in[1];
    const int*   mask  = (const int*)d_in[2];
    const float* trans = (const float*)d_in[3];
    const float* start = (const float*)d_in[4];
    const float* endv  = (const float*)d_in[5];
    float* out = (float*)d_out;

    crf_den_kernel<<<B_, 256>>>(pred, mask, trans, start, endv);
    crf_num_kernel<<<B_, 256>>>(pred, tgt, mask, trans, start, endv);
    crf_final_kernel<<<1, B_>>>(out);
}